// round 16
// baseline (speedup 1.0000x reference)
#include <cuda_runtime.h>
#include <cuda_bf16.h>
#include <math.h>

#define BDIM 512
#define DDIM 512
#define CDIM 100000
#define SCALE_F 64.0f
#define MARGIN_F 0.35f

#define TILE_N 256                      // 4 groups x 64 cols
#define NT 391                          // ceil(100000/256); 391*256=100096
#define C_PAD (NT * TILE_N)             // 100096
#define NPART (NT * 8)                  // per-row partials: 4 groups x 2 wn
#define GRIDX 37                        // 37*4 = 148 CTAs = 1 wave

#define ASTRIDE_B 1040                  // A smem row stride (512*2 + 16)
#define BSTRIDE_B 144                   // B smem row stride (64*2 + 16)
#define A_SMEM_BYTES (128 * ASTRIDE_B)              // 133120
#define G_STAGE (64 * BSTRIDE_B)                    // 9216
#define OFF_B A_SMEM_BYTES
#define SMEM_DYN (OFF_B + 4 * 2 * G_STAGE)          // 206848 < 227KB

// ---------------- device scratch ----------------
__device__ __nv_bfloat16 g_xb[BDIM * DDIM];
__device__ float         g_xn[BDIM * DDIM];
__device__ __nv_bfloat16 g_wb[(size_t)C_PAD * DDIM];   // bf16 W (~102.5 MB)
__device__ float         g_rss[C_PAD];                 // exact fp32 ||w||^2
__device__ float         g_pm[(size_t)BDIM * NPART];
__device__ float         g_ps[(size_t)BDIM * NPART];
__device__ float         g_cosgt[BDIM];
__device__ float         g_nll[BDIM];
__device__ int           g_is64;

// ---------------- helpers ----------------
__device__ __forceinline__ unsigned smem_u32(const void* p) {
    unsigned a;
    asm("{ .reg .u64 t; cvta.to.shared.u64 t, %1; cvt.u32.u64 %0, t; }" : "=r"(a) : "l"(p));
    return a;
}
#define BAR_G(id) asm volatile("bar.sync %0, 128;" :: "r"(id) : "memory")
#define CP_ASYNC16(d, s) asm volatile("cp.async.cg.shared.global [%0], [%1], 16;" :: "r"(d), "l"(s) : "memory")
#define CP_COMMIT()  asm volatile("cp.async.commit_group;" ::: "memory")
#define CP_WAIT0()   asm volatile("cp.async.wait_group 0;" ::: "memory")

// ---------------- small kernels ----------------
__global__ void detect_gt_kernel(const int* __restrict__ graw) {
    __shared__ int any_nz;
    if (threadIdx.x == 0) any_nz = 0;
    __syncthreads();
    if ((threadIdx.x & 1) && graw[threadIdx.x] != 0) any_nz = 1;
    __syncthreads();
    if (threadIdx.x == 0) g_is64 = any_nz ? 0 : 1;
}

__global__ void __launch_bounds__(128) norm_x_kernel(const float* __restrict__ x) {
    int b = blockIdx.x, tid = threadIdx.x;
    float4 v = ((const float4*)(x + (size_t)b * DDIM))[tid];
    float ss = v.x*v.x + v.y*v.y + v.z*v.z + v.w*v.w;
    #pragma unroll
    for (int o = 16; o; o >>= 1) ss += __shfl_xor_sync(0xffffffffu, ss, o);
    __shared__ float sm[4];
    if ((tid & 31) == 0) sm[tid >> 5] = ss;
    __syncthreads();
    float tot = sm[0] + sm[1] + sm[2] + sm[3];
    float r = 1.0f / fmaxf(sqrtf(tot), 1e-12f);
    float4 n = make_float4(v.x*r, v.y*r, v.z*r, v.w*r);
    ((float4*)(g_xn + (size_t)b * DDIM))[tid] = n;
    __nv_bfloat162* dst = (__nv_bfloat162*)(g_xb + (size_t)b * DDIM);
    dst[tid * 2 + 0] = __floats2bfloat162_rn(n.x, n.y);
    dst[tid * 2 + 1] = __floats2bfloat162_rn(n.z, n.w);
}

// W fp32 -> bf16 copy + exact fp32 row sum-of-squares (no normalization pass)
__global__ void __launch_bounds__(128) cvt_w_kernel(const float* __restrict__ wt) {
    int c = blockIdx.x, tid = threadIdx.x;
    __nv_bfloat162* dst = (__nv_bfloat162*)(g_wb + (size_t)c * DDIM);
    if (c >= CDIM) {
        __nv_bfloat162 z = __floats2bfloat162_rn(0.f, 0.f);
        dst[tid * 2 + 0] = z;
        dst[tid * 2 + 1] = z;
        if (tid == 0) g_rss[c] = 0.0f;
        return;
    }
    float4 v = ((const float4*)(wt + (size_t)c * DDIM))[tid];
    float ss = v.x*v.x + v.y*v.y + v.z*v.z + v.w*v.w;
    #pragma unroll
    for (int o = 16; o; o >>= 1) ss += __shfl_xor_sync(0xffffffffu, ss, o);
    __shared__ float sm[4];
    if ((tid & 31) == 0) sm[tid >> 5] = ss;
    __syncthreads();
    dst[tid * 2 + 0] = __floats2bfloat162_rn(v.x, v.y);
    dst[tid * 2 + 1] = __floats2bfloat162_rn(v.z, v.w);
    if (tid == 0) g_rss[c] = sm[0] + sm[1] + sm[2] + sm[3];
}

__global__ void __launch_bounds__(128) cosgt_kernel(const void* __restrict__ gt,
                                                    const float* __restrict__ wt) {
    int b = blockIdx.x, tid = threadIdx.x;
    long long c = g_is64 ? ((const long long*)gt)[b] : (long long)((const int*)gt)[b];
    float4 w  = ((const float4*)(wt + (size_t)c * DDIM))[tid];
    float4 xn = ((const float4*)(g_xn + (size_t)b * DDIM))[tid];
    float ss = w.x*w.x + w.y*w.y + w.z*w.z + w.w*w.w;
    float dp = w.x*xn.x + w.y*xn.y + w.z*xn.z + w.w*xn.w;
    #pragma unroll
    for (int o = 16; o; o >>= 1) {
        ss += __shfl_xor_sync(0xffffffffu, ss, o);
        dp += __shfl_xor_sync(0xffffffffu, dp, o);
    }
    __shared__ float sms[4], smd[4];
    if ((tid & 31) == 0) { sms[tid >> 5] = ss; smd[tid >> 5] = dp; }
    __syncthreads();
    if (tid == 0) {
        float tss = sms[0] + sms[1] + sms[2] + sms[3];
        float tdp = smd[0] + smd[1] + smd[2] + smd[3];
        g_cosgt[b] = tdp / fmaxf(sqrtf(tss), 1e-12f);
    }
}

// ---------------- GEMM: 4 independent 4-warp groups, cp.async 2-stage rings ----------------
// grid (37, 4), 512 threads. Group g (warps 4g..4g+3) owns cols
// [nt*256 + g*64, +64); its own 2-stage ring + named barrier. Warp tile 64x32.
__global__ void __launch_bounds__(512, 1) gemm_softmax_kernel() {
    extern __shared__ char smem[];
    unsigned sbA = smem_u32(smem);

    int tid  = threadIdx.x;
    int lane = tid & 31;
    int warp = tid >> 5;
    int g    = warp >> 2;       // group 0..3
    int gw   = warp & 3;
    int wm   = gw >> 1;         // 0..1 (64-row warp tiles)
    int wn   = gw & 1;          // 0..1 (32-col warp tiles)
    int m0 = blockIdx.y * 128;
    int bx = blockIdx.x;
    int barid = g + 1;

    int gtid = tid & 127;
    int seg  = gtid & 7;        // 16B segment of 128B bf16 chunk row
    int rowb = gtid >> 3;       // 0..15
    const char* wb = (const char*)g_wb;

    unsigned stg = sbA + OFF_B + g * (2 * G_STAGE);

    int ntiles = (NT - bx + GRIDX - 1) / GRIDX;
    int NC = ntiles * 8;

    // ---- stage A[128x512] bf16 (all 512 threads) ----
    #pragma unroll
    for (int it = 0; it < 16; it++) {
        int idx = it * 512 + tid;
        int r = idx >> 6, s = idx & 63;
        uint4 v = *(const uint4*)(g_xb + (size_t)(m0 + r) * DDIM + s * 8);
        *(uint4*)(smem + r * ASTRIDE_B + s * 16) = v;
    }
    __syncthreads();

    // cp.async one chunk (global index s) into stage sst
    auto CPCHUNK = [&](int s, int sst) {
        int ts = s >> 3, ck = s & 7;
        int rbase = (bx + ts * GRIDX) * TILE_N + g * 64;
        unsigned dbase = stg + sst * G_STAGE + seg * 16;
        const char* src = wb + (size_t)rbase * 1024 + ck * 128 + seg * 16;
        #pragma unroll
        for (int q = 0; q < 4; q++) {
            int row = rowb + q * 16;
            CP_ASYNC16(dbase + row * BSTRIDE_B, src + (size_t)row * 1024);
        }
        CP_COMMIT();
    };

    CPCHUNK(0, 0);   // prologue: prefetch distance 1

    int g4 = lane >> 2, t4 = lane & 3;
    int aColOff = (lane >> 4) << 3;

    float acc[4][4][4];
    #pragma unroll 1
    for (int c = 0; c < NC; c++) {
        int ck = c & 7;
        if (ck == 0) {
            #pragma unroll
            for (int i = 0; i < 4; i++)
                #pragma unroll
                for (int j = 0; j < 4; j++)
                    #pragma unroll
                    for (int e = 0; e < 4; e++) acc[i][j][e] = 0.0f;
        }
        CP_WAIT0();          // chunk c resident (own segments)
        BAR_G(barid);        // peers done waiting + stage (c+1)&1 free

        if (c + 1 < NC) CPCHUNK(c + 1, (c + 1) & 1);

        // ---- MMA over stage c&1: 4 k16 steps ----
        unsigned bB = stg + (c & 1) * G_STAGE;
        #pragma unroll
        for (int k16 = 0; k16 < 4; k16++) {
            unsigned a[4][4];
            #pragma unroll
            for (int i = 0; i < 4; i++) {
                int r   = wm * 64 + i * 16 + (lane & 15);
                int col = ck * 64 + k16 * 16 + aColOff;
                unsigned addr = sbA + r * ASTRIDE_B + col * 2;
                asm volatile("ldmatrix.sync.aligned.m8n8.x4.shared.b16 {%0,%1,%2,%3}, [%4];"
                             : "=r"(a[i][0]), "=r"(a[i][1]), "=r"(a[i][2]), "=r"(a[i][3])
                             : "r"(addr));
            }
            unsigned bfr[4][2];
            #pragma unroll
            for (int j2 = 0; j2 < 2; j2++) {
                int nrow = wn * 32 + j2 * 16 + (lane & 7) + ((lane >> 4) << 3);
                int col  = k16 * 16 + (((lane >> 3) & 1) << 3);
                unsigned addr = bB + nrow * BSTRIDE_B + col * 2;
                unsigned r0, r1, r2, r3;
                asm volatile("ldmatrix.sync.aligned.m8n8.x4.shared.b16 {%0,%1,%2,%3}, [%4];"
                             : "=r"(r0), "=r"(r1), "=r"(r2), "=r"(r3) : "r"(addr));
                bfr[j2 * 2 + 0][0] = r0; bfr[j2 * 2 + 0][1] = r1;
                bfr[j2 * 2 + 1][0] = r2; bfr[j2 * 2 + 1][1] = r3;
            }
            #pragma unroll
            for (int i = 0; i < 4; i++)
                #pragma unroll
                for (int j = 0; j < 4; j++)
                    asm volatile(
                        "mma.sync.aligned.m16n8k16.row.col.f32.bf16.bf16.f32 "
                        "{%0,%1,%2,%3},{%4,%5,%6,%7},{%8,%9},{%0,%1,%2,%3};"
                        : "+f"(acc[i][j][0]), "+f"(acc[i][j][1]),
                          "+f"(acc[i][j][2]), "+f"(acc[i][j][3])
                        : "r"(a[i][0]), "r"(a[i][1]), "r"(a[i][2]), "r"(a[i][3]),
                          "r"(bfr[j][0]), "r"(bfr[j][1]));
        }

        if (ck == 7) {
            // ---- per-warp epilogue for tile tp ----
            int tp = c >> 3;
            int nt = bx + tp * GRIDX;
            int n0 = nt * TILE_N + g * 64;
            float rn[8];
            #pragma unroll
            for (int j = 0; j < 4; j++)
                #pragma unroll
                for (int e2 = 0; e2 < 2; e2++) {
                    int tc = n0 + wn * 32 + j * 8 + t4 * 2 + e2;
                    rn[j * 2 + e2] = rsqrtf(fmaxf(g_rss[tc], 1e-30f)) * SCALE_F;
                }
            #pragma unroll
            for (int i = 0; i < 4; i++) {
                #pragma unroll
                for (int h = 0; h < 2; h++) {
                    float m = -INFINITY;
                    #pragma unroll
                    for (int j = 0; j < 4; j++)
                        #pragma unroll
                        for (int e2 = 0; e2 < 2; e2++) {
                            int gc = n0 + wn * 32 + j * 8 + t4 * 2 + e2;
                            if (gc < CDIM)
                                m = fmaxf(m, rn[j * 2 + e2] * acc[i][j][h * 2 + e2]);
                        }
                    m = fmaxf(m, __shfl_xor_sync(0xffffffffu, m, 1));
                    m = fmaxf(m, __shfl_xor_sync(0xffffffffu, m, 2));
                    float s = 0.0f;
                    if (m > -1e37f) {
                        #pragma unroll
                        for (int j = 0; j < 4; j++)
                            #pragma unroll
                            for (int e2 = 0; e2 < 2; e2++) {
                                int gc = n0 + wn * 32 + j * 8 + t4 * 2 + e2;
                                if (gc < CDIM)
                                    s += __expf(rn[j * 2 + e2] * acc[i][j][h * 2 + e2] - m);
                            }
                    }
                    s += __shfl_xor_sync(0xffffffffu, s, 1);
                    s += __shfl_xor_sync(0xffffffffu, s, 2);
                    if (t4 == 0) {
                        int r = m0 + wm * 64 + i * 16 + h * 8 + g4;
                        size_t idx = (size_t)r * NPART + nt * 8 + g * 2 + wn;
                        g_pm[idx] = fmaxf(m, -3.0e38f);
                        g_ps[idx] = s;
                    }
                }
            }
        }
    }
}

// ---------------- logsumexp merge + margin + NLL ----------------
__global__ void __launch_bounds__(256) reduce_kernel() {
    int b = blockIdx.x, tid = threadIdx.x;
    float M = -INFINITY, S = 0.0f;
    for (int i = tid; i < NPART; i += 256) {
        float m = g_pm[(size_t)b * NPART + i];
        float s = g_ps[(size_t)b * NPART + i];
        if (m > M) { S = S * __expf(M - m) + s; M = m; }
        else       { S += s * __expf(m - M); }
    }
    __shared__ float sm[256], ss[256];
    sm[tid] = M; ss[tid] = S;
    __syncthreads();
    for (int o = 128; o; o >>= 1) {
        if (tid < o) {
            float m2 = sm[tid + o], s2 = ss[tid + o];
            float m1 = sm[tid],     s1 = ss[tid];
            float mn = fmaxf(m1, m2);
            sm[tid] = mn;
            ss[tid] = s1 * __expf(m1 - mn) + s2 * __expf(m2 - mn);
        }
        __syncthreads();
    }
    if (tid == 0) {
        float Mf = sm[0], Sf = ss[0];
        float zg = SCALE_F * g_cosgt[b];
        float zm = zg - SCALE_F * MARGIN_F;
        Sf = Sf - expf(zg - Mf) + expf(zm - Mf);
        float lse = Mf + logf(Sf);
        g_nll[b] = lse - zm;
    }
}

__global__ void __launch_bounds__(512) mean_kernel(float* __restrict__ out) {
    __shared__ float sm[512];
    int t = threadIdx.x;
    sm[t] = g_nll[t];
    __syncthreads();
    for (int o = 256; o; o >>= 1) {
        if (t < o) sm[t] += sm[t + o];
        __syncthreads();
    }
    if (t == 0) out[0] = sm[0] * (1.0f / (float)BDIM);
}

// ---------------- launch ----------------
extern "C" void kernel_launch(void* const* d_in, const int* in_sizes, int n_in,
                              void* d_out, int out_size) {
    const float* x  = (const float*)d_in[0];
    const void*  gt = d_in[1];
    const float* wt = (const float*)d_in[2];
    float* out = (float*)d_out;

    static int smem_set = 0;
    if (!smem_set) {
        cudaFuncSetAttribute(gemm_softmax_kernel,
                             cudaFuncAttributeMaxDynamicSharedMemorySize, SMEM_DYN);
        smem_set = 1;
    }

    detect_gt_kernel<<<1, 512>>>((const int*)gt);
    norm_x_kernel<<<BDIM, 128>>>(x);
    cvt_w_kernel<<<C_PAD, 128>>>(wt);
    cosgt_kernel<<<BDIM, 128>>>(gt, wt);
    gemm_softmax_kernel<<<dim3(GRIDX, 4), 512, SMEM_DYN>>>();
    reduce_kernel<<<BDIM, 256>>>();
    mean_kernel<<<1, 512>>>(out);
}